// round 14
// baseline (speedup 1.0000x reference)
#include <cuda_runtime.h>
#include <cuda_fp16.h>
#include <math.h>
#include <stdint.h>

#define NPOS 4096
#define QK_SCALE 0.2041241452319315f  /* 24^-0.5 */
#define KSPLIT 2

// Scratch (device globals — no allocation allowed)
__device__ __half g_qkv16[576 * NPOS];            // qkv after 1x1 conv, fp16 [o][p]
__device__ __half g_q16[8 * NPOS * 24];           // normalized q (scale folded), [h][p][d]
__device__ __half g_k16[8 * NPOS * 24];           // normalized k, [h][p][d]
__device__ __half g_v16[8 * NPOS * 24];           // v, [h][p][d]
__device__ float  g_pacc[8 * KSPLIT * 24 * NPOS]; // split-K partial acc
__device__ float  g_pl[8 * KSPLIT * NPOS];        // split-K partial l

__device__ __forceinline__ uint32_t s2u(const void* p){
    uint32_t a;
    asm("{ .reg .u64 t; cvta.to.shared.u64 t, %1; cvt.u32.u64 %0, t; }" : "=r"(a) : "l"(p));
    return a;
}
#define LDSM_X4(r0,r1,r2,r3,a) \
    asm volatile("ldmatrix.sync.aligned.m8n8.x4.shared.b16 {%0,%1,%2,%3}, [%4];" \
        : "=r"(r0), "=r"(r1), "=r"(r2), "=r"(r3) : "r"(a))
#define LDSM_X4T(r0,r1,r2,r3,a) \
    asm volatile("ldmatrix.sync.aligned.m8n8.x4.trans.shared.b16 {%0,%1,%2,%3}, [%4];" \
        : "=r"(r0), "=r"(r1), "=r"(r2), "=r"(r3) : "r"(a))
#define LDSM_X2T(r0,r1,a) \
    asm volatile("ldmatrix.sync.aligned.m8n8.x2.trans.shared.b16 {%0,%1}, [%2];" \
        : "=r"(r0), "=r"(r1) : "r"(a))
#define MMA16816(c0,c1,c2,c3,a0,a1,a2,a3,b0,b1) \
    asm volatile("mma.sync.aligned.m16n8k16.row.col.f32.f16.f16.f32 " \
        "{%0,%1,%2,%3}, {%4,%5,%6,%7}, {%8,%9}, {%0,%1,%2,%3};" \
        : "+f"(c0), "+f"(c1), "+f"(c2), "+f"(c3) \
        : "r"(a0), "r"(a1), "r"(a2), "r"(a3), "r"(b0), "r"(b1))
#define CP16(dst, src) \
    asm volatile("cp.async.cg.shared.global [%0], [%1], 16;" :: "r"(dst), "l"(src))

// ---------------------------------------------------------------------------
// qkv 1x1 conv via fp16 mma: out16[o][p] = sum_c w[o][c] * x[c][p]  (f32 x)
// CTA: 128 thr / 4 warps, tile O=64 x P=64. Grid: (64, 9).
// ---------------------------------------------------------------------------
__global__ __launch_bounds__(128) void pw1_mma_kernel(
    __half* __restrict__ out16, const float* __restrict__ x,
    const float* __restrict__ w)
{
    __shared__ __align__(16) __half sA[64 * 200];  // [o][k], pad 192->200
    __shared__ __align__(16) __half sB[16 * 72];   // [k16][p64], pad 64->72

    const int tid  = threadIdx.x;
    const int lane = tid & 31, warp = tid >> 5;
    const int p0 = blockIdx.x * 64;
    const int o0 = blockIdx.y * 64;

    {
        const float4* wg = (const float4*)(w + o0 * 192);
#pragma unroll
        for (int i = 0; i < 24; i++) {
            int e = i * 128 + tid;
            int r = e / 48, m = e - 48 * r;
            float4 f = wg[e];
            *(__half2*)(sA + r * 200 + m * 4)     = __floats2half2_rn(f.x, f.y);
            *(__half2*)(sA + r * 200 + m * 4 + 2) = __floats2half2_rn(f.z, f.w);
        }
    }

    float acc[8][4] = {};

    float4 pf[2];
#pragma unroll
    for (int i = 0; i < 2; i++) {
        int e = i * 128 + tid;
        int kk = e >> 4, m = e & 15;
        pf[i] = *(const float4*)(x + kk * NPOS + p0 + m * 4);
    }

    const uint32_t sA_s = s2u(sA), sB_s = s2u(sB);

    for (int ks = 0; ks < 12; ks++) {
        __syncthreads();
#pragma unroll
        for (int i = 0; i < 2; i++) {
            int e = i * 128 + tid;
            int kk = e >> 4, m = e & 15;
            *(__half2*)(sB + kk * 72 + m * 4)     = __floats2half2_rn(pf[i].x, pf[i].y);
            *(__half2*)(sB + kk * 72 + m * 4 + 2) = __floats2half2_rn(pf[i].z, pf[i].w);
        }
        __syncthreads();

        if (ks + 1 < 12) {
#pragma unroll
            for (int i = 0; i < 2; i++) {
                int e = i * 128 + tid;
                int kk = e >> 4, m = e & 15;
                pf[i] = *(const float4*)(x + ((ks + 1) * 16 + kk) * NPOS + p0 + m * 4);
            }
        }

        uint32_t a0, a1, a2, a3;
        LDSM_X4(a0, a1, a2, a3,
                sA_s + (((warp * 16 + (lane & 15)) * 200 + ks * 16 + (lane >> 4) * 8) << 1));
#pragma unroll
        for (int c = 0; c < 4; c++) {
            uint32_t b0, b1, b2, b3;
            LDSM_X4T(b0, b1, b2, b3,
                     sB_s + (((lane & 15) * 72 + c * 16 + (lane >> 4) * 8) << 1));
            MMA16816(acc[2*c][0], acc[2*c][1], acc[2*c][2], acc[2*c][3],
                     a0, a1, a2, a3, b0, b1);
            MMA16816(acc[2*c+1][0], acc[2*c+1][1], acc[2*c+1][2], acc[2*c+1][3],
                     a0, a1, a2, a3, b2, b3);
        }
    }

    const int gid = lane >> 2, tig = lane & 3;
    const int o = o0 + warp * 16 + gid;
#pragma unroll
    for (int c8 = 0; c8 < 8; c8++) {
        int p = p0 + c8 * 8 + tig * 2;
        *(__half2*)&out16[o * NPOS + p]       = __floats2half2_rn(acc[c8][0], acc[c8][1]);
        *(__half2*)&out16[(o + 8) * NPOS + p] = __floats2half2_rn(acc[c8][2], acc[c8][3]);
    }
}

// ---------------------------------------------------------------------------
// proj 1x1 conv via fp16 mma with FUSED split-K combine, double-buffered B:
//   a16[c][p] = (pacc_s0[c][p] + pacc_s1[c][p]) / (l0[h][p] + l1[h][p])
// One sync per ks; B store overlaps MMA. Grid: (64, 3). f32 out.
// ---------------------------------------------------------------------------
__global__ __launch_bounds__(128) void pw2_mma_kernel(
    float* __restrict__ out, const float* __restrict__ pacc,
    const float* __restrict__ pl, const float* __restrict__ w)
{
    __shared__ __align__(16) __half sA[64 * 200];
    __shared__ __align__(16) __half sB[2][16 * 72];
    __shared__ __align__(16) float  sLinv[512];   // [head 8][p 64]

    const int tid  = threadIdx.x;
    const int lane = tid & 31, warp = tid >> 5;
    const int p0 = blockIdx.x * 64;
    const int o0 = blockIdx.y * 64;

    {
        const float4* wg = (const float4*)(w + o0 * 192);
#pragma unroll
        for (int i = 0; i < 24; i++) {
            int e = i * 128 + tid;
            int r = e / 48, m = e - 48 * r;
            float4 f = wg[e];
            *(__half2*)(sA + r * 200 + m * 4)     = __floats2half2_rn(f.x, f.y);
            *(__half2*)(sA + r * 200 + m * 4 + 2) = __floats2half2_rn(f.z, f.w);
        }
    }
    // linv table: 8 heads x 64 positions
#pragma unroll
    for (int i = 0; i < 4; i++) {
        int idx = i * 128 + tid;
        int h = idx >> 6, pp = idx & 63;
        float l = pl[(h * 2) * NPOS + p0 + pp] + pl[(h * 2 + 1) * NPOS + p0 + pp];
        sLinv[idx] = 1.0f / l;
    }

    float acc[8][4] = {};

    const int br = tid >> 3;            // B row 0..15
    const int m8 = (tid & 7) * 8;       // p offset 0..56

    float4 pa0, pa1, pb0, pb1;
    auto loadB = [&](int ks) {
        int c = ks * 16 + br;
        int h = (c * 21846) >> 19;      // c / 24
        int d = c - h * 24;
        const float* s0 = pacc + ((h * 2) * 24 + d) * NPOS + p0 + m8;
        const float* s1 = s0 + 24 * NPOS;
        pa0 = *(const float4*)s0;  pb0 = *(const float4*)(s0 + 4);
        pa1 = *(const float4*)s1;  pb1 = *(const float4*)(s1 + 4);
    };
    auto storeB = [&](int ks) {
        int c = ks * 16 + br;
        int h = (c * 21846) >> 19;
        const float* li = sLinv + h * 64 + m8;
        float4 l0 = *(const float4*)li, l1 = *(const float4*)(li + 4);
        float v0 = (pa0.x + pa1.x) * l0.x;
        float v1 = (pa0.y + pa1.y) * l0.y;
        float v2 = (pa0.z + pa1.z) * l0.z;
        float v3 = (pa0.w + pa1.w) * l0.w;
        float v4 = (pb0.x + pb1.x) * l1.x;
        float v5 = (pb0.y + pb1.y) * l1.y;
        float v6 = (pb0.z + pb1.z) * l1.z;
        float v7 = (pb0.w + pb1.w) * l1.w;
        __half* d8 = sB[ks & 1] + br * 72 + m8;
        *(__half2*)(d8)     = __floats2half2_rn(v0, v1);
        *(__half2*)(d8 + 2) = __floats2half2_rn(v2, v3);
        *(__half2*)(d8 + 4) = __floats2half2_rn(v4, v5);
        *(__half2*)(d8 + 6) = __floats2half2_rn(v6, v7);
    };

    loadB(0);
    __syncthreads();      // sLinv ready for all threads
    storeB(0);

    const uint32_t sA_s = s2u(sA), sB_s = s2u(&sB[0][0]);

    for (int ks = 0; ks < 12; ks++) {
        if (ks + 1 < 12) loadB(ks + 1);
        __syncthreads();  // buf[ks&1] stores visible; prior reads of buf[(ks+1)&1] done
        if (ks + 1 < 12) storeB(ks + 1);   // writes buf[(ks+1)&1], overlaps MMA below

        const uint32_t bo = (uint32_t)(ks & 1) * (16 * 72 * 2);
        uint32_t a0, a1, a2, a3;
        LDSM_X4(a0, a1, a2, a3,
                sA_s + (((warp * 16 + (lane & 15)) * 200 + ks * 16 + (lane >> 4) * 8) << 1));
#pragma unroll
        for (int c = 0; c < 4; c++) {
            uint32_t b0, b1, b2, b3;
            LDSM_X4T(b0, b1, b2, b3,
                     sB_s + bo + (((lane & 15) * 72 + c * 16 + (lane >> 4) * 8) << 1));
            MMA16816(acc[2*c][0], acc[2*c][1], acc[2*c][2], acc[2*c][3],
                     a0, a1, a2, a3, b0, b1);
            MMA16816(acc[2*c+1][0], acc[2*c+1][1], acc[2*c+1][2], acc[2*c+1][3],
                     a0, a1, a2, a3, b2, b3);
        }
    }

    const int gid = lane >> 2, tig = lane & 3;
    const int o = o0 + warp * 16 + gid;
#pragma unroll
    for (int c8 = 0; c8 < 8; c8++) {
        int p = p0 + c8 * 8 + tig * 2;
        *(float2*)&out[o * NPOS + p]       = make_float2(acc[c8][0], acc[c8][1]);
        *(float2*)&out[(o + 8) * NPOS + p] = make_float2(acc[c8][2], acc[c8][3]);
    }
}

// ---------------------------------------------------------------------------
// Fused: depthwise 3x3 (padding=1, fp16 input) + L2-normalize (24) + fp16 out.
// ---------------------------------------------------------------------------
__global__ __launch_bounds__(256) void dwnorm_kernel(
    const __half* __restrict__ in, const float* __restrict__ wdw,
    __half* __restrict__ q16, __half* __restrict__ k16, __half* __restrict__ v16)
{
    const int g = blockIdx.x * 256 + threadIdx.x;
    const int t = g >> 15;          // 0=q, 1=k, 2=v
    const int rem = g & 32767;
    const int h = rem >> 12;
    const int p = rem & 4095;
    const int y = p >> 6, x = p & 63;

    const __half* ipb = in + (t * 192 + h * 24) * NPOS;
    const float* wpb = wdw + (t * 192 + h * 24) * 9;

    const bool ym = (y > 0), yp = (y < 63);
    const bool xm = (x > 0), xp = (x < 63);

    float v[24];
    float ss = 0.f;
#pragma unroll
    for (int d = 0; d < 24; d++) {
        const __half* ip = ipb + d * NPOS + p;
        const float* wp = wpb + d * 9;
        float a = wp[4] * __half2float(ip[0]);
        if (ym) {
            a += wp[1] * __half2float(ip[-64]);
            if (xm) a += wp[0] * __half2float(ip[-65]);
            if (xp) a += wp[2] * __half2float(ip[-63]);
        }
        if (xm) a += wp[3] * __half2float(ip[-1]);
        if (xp) a += wp[5] * __half2float(ip[1]);
        if (yp) {
            a += wp[7] * __half2float(ip[64]);
            if (xm) a += wp[6] * __half2float(ip[63]);
            if (xp) a += wp[8] * __half2float(ip[65]);
        }
        v[d] = a;
        ss += a * a;
    }
    float inv;
    if (t == 0)      inv = QK_SCALE / fmaxf(sqrtf(ss), 1e-12f);
    else if (t == 1) inv = 1.0f / fmaxf(sqrtf(ss), 1e-12f);
    else             inv = 1.0f;

    __half* o = (t == 0 ? q16 : (t == 1 ? k16 : v16)) + (h * NPOS + p) * 24;
#pragma unroll
    for (int d = 0; d < 24; d++)
        o[d] = __float2half_rn(v[d] * inv);
}

// ---------------------------------------------------------------------------
// Flash attention via mma.sync m16n8k16, split-K=2, double-buffered cp.async.
// exp via degree-3 Taylor in HALF2 (scores bounded ±0.205, common-mode with l).
// Row-sum l computed BY the tensor core: V smem col 24 = 1.0 -> 4th PV MMA
// accumulates l in fp32 from the same half p used for PV.
// Grid: (64 row tiles, 8 heads, KSPLIT).
// ---------------------------------------------------------------------------
__global__ __launch_bounds__(128) void attn_kernel(
    float* __restrict__ pacc, float* __restrict__ pl,
    const __half* __restrict__ q16, const __half* __restrict__ k16,
    const __half* __restrict__ v16)
{
    __shared__ __align__(16) __half sQ[64 * 40];
    __shared__ __align__(16) __half sK[2][128 * 40];
    __shared__ __align__(16) __half sV[2][128 * 40];

    const int tid   = threadIdx.x;
    const int lane  = tid & 31, warp = tid >> 5;
    const int head  = blockIdx.y;
    const int split = blockIdx.z;
    const int row0  = blockIdx.x * 64;

    uint32_t* sQu = (uint32_t*)sQ;
    uint32_t* sKu = (uint32_t*)sK;
    uint32_t* sVu = (uint32_t*)sV;

    {
        const uint32_t* qg = (const uint32_t*)(q16 + (head * NPOS + row0) * 24);
#pragma unroll
        for (int i = 0; i < 6; i++) {
            int e = i * 128 + tid;
            int r = e / 12, u = e - 12 * r;
            sQu[r * 20 + u] = qg[e];
        }
#pragma unroll
        for (int i = 0; i < 2; i++) {
            int e = i * 128 + tid;
            int r = e >> 2, u = e & 3;
            sQu[r * 20 + 12 + u] = 0u;
        }
        // K pad d24..31 = 0 (both buffers); V pad: col24 = 1.0, cols25..31 = 0
#pragma unroll
        for (int i = 0; i < 8; i++) {
            int e = i * 128 + tid;
            int r = e >> 2, u = e & 3;
            sKu[r * 20 + 12 + u] = 0u;
            sVu[r * 20 + 12 + u] = (u == 0) ? 0x00003C00u : 0u;
        }
    }
    __syncthreads();

    uint32_t aq[2][4];
    {
        uint32_t qa = s2u(sQ) + (((warp * 16 + (lane & 15)) * 40 + (lane >> 4) * 8) << 1);
        LDSM_X4(aq[0][0], aq[0][1], aq[0][2], aq[0][3], qa);
        LDSM_X4(aq[1][0], aq[1][1], aq[1][2], aq[1][3], qa + 32);
    }

    float co[4][4] = {};   // co[3] = l column (n24..31; col24 = row sum)

    const __half2 eC  = __floats2half2_rn(0.16666667f, 0.16666667f);
    const __half2 eH  = __floats2half2_rn(0.5f, 0.5f);
    const __half2 eONE = __floats2half2_rn(1.0f, 1.0f);

    const uint32_t sK_s = s2u(sK), sV_s = s2u(sV);
    const uint32_t ka0 = sK_s + ((((lane & 7) * 40) + (lane >> 3) * 8) << 1);
    const uint32_t va0 = sV_s + ((((lane & 15) * 40) + (lane >> 4) * 8) << 1);
    const uint32_t va2 = sV_s + ((((lane & 15) * 40) + 16) << 1);
    const uint32_t va3 = sV_s + ((((lane & 15) * 40) + 24) << 1);

    const uint4* kg4 = (const uint4*)(k16 + head * NPOS * 24);
    const uint4* vg4 = (const uint4*)(v16 + head * NPOS * 24);
    const int tbase = split * (32 / KSPLIT);
    const int NT = 32 / KSPLIT;

    auto stage = [&](int tt, int b) {
        const uint4* kg = kg4 + (tbase + tt) * 384;
        const uint4* vg = vg4 + (tbase + tt) * 384;
        const uint32_t bo = (uint32_t)b * 10240u;
#pragma unroll
        for (int i = 0; i < 3; i++) {
            int e = i * 128 + tid;
            int r = e / 3, m = e - 3 * r;
            uint32_t off = bo + (uint32_t)(r * 80 + m * 16);
            CP16(sK_s + off, kg + e);
            CP16(sV_s + off, vg + e);
        }
        asm volatile("cp.async.commit_group;" ::: "memory");
    };

    stage(0, 0);

    for (int t = 0; t < NT; t++) {
        if (t + 1 < NT) {
            stage(t + 1, (t + 1) & 1);
            asm volatile("cp.async.wait_group 1;" ::: "memory");
        } else {
            asm volatile("cp.async.wait_group 0;" ::: "memory");
        }
        __syncthreads();

        const uint32_t bo = (uint32_t)(t & 1) * 10240u;

        uint32_t ap[16][2];
#pragma unroll
        for (int nt = 0; nt < 16; nt++) {
            uint32_t b0, b1, b2, b3;
            LDSM_X4(b0, b1, b2, b3, ka0 + bo + nt * 640);
            float c0 = 0.f, c1 = 0.f, c2 = 0.f, c3 = 0.f;
            MMA16816(c0, c1, c2, c3, aq[0][0], aq[0][1], aq[0][2], aq[0][3], b0, b1);
            MMA16816(c0, c1, c2, c3, aq[1][0], aq[1][1], aq[1][2], aq[1][3], b2, b3);
            // exp3 in half2: |s| <= 0.205; errors common-mode with l (same p's)
            __half2 s01 = __floats2half2_rn(c0, c1);
            __half2 s23 = __floats2half2_rn(c2, c3);
            __half2 t01 = __hfma2(eC, s01, eH);
            __half2 t23 = __hfma2(eC, s23, eH);
            t01 = __hfma2(t01, s01, eONE);
            t23 = __hfma2(t23, s23, eONE);
            t01 = __hfma2(t01, s01, eONE);
            t23 = __hfma2(t23, s23, eONE);
            ap[nt][0] = *(uint32_t*)&t01;
            ap[nt][1] = *(uint32_t*)&t23;
        }

#pragma unroll
        for (int s = 0; s < 8; s++) {
            uint32_t b0, b1, b2, b3, b4, b5, b6, b7;
            LDSM_X4T(b0, b1, b2, b3, va0 + bo + s * 1280);
            LDSM_X2T(b4, b5, va2 + bo + s * 1280);
            LDSM_X2T(b6, b7, va3 + bo + s * 1280);
            uint32_t A0 = ap[2 * s][0], A1 = ap[2 * s][1];
            uint32_t A2 = ap[2 * s + 1][0], A3 = ap[2 * s + 1][1];
            MMA16816(co[0][0], co[0][1], co[0][2], co[0][3], A0, A1, A2, A3, b0, b1);
            MMA16816(co[1][0], co[1][1], co[1][2], co[1][3], A0, A1, A2, A3, b2, b3);
            MMA16816(co[2][0], co[2][1], co[2][2], co[2][3], A0, A1, A2, A3, b4, b5);
            MMA16816(co[3][0], co[3][1], co[3][2], co[3][3], A0, A1, A2, A3, b6, b7);
        }
        __syncthreads();
    }

    const int gid = lane >> 2, tig = lane & 3;
    const int r0 = row0 + warp * 16 + gid;
    const int sb = head * KSPLIT + split;

    float* pa = pacc + sb * 24 * NPOS;
#pragma unroll
    for (int nt = 0; nt < 3; nt++) {
        int d = nt * 8 + tig * 2;
        pa[(d) * NPOS + r0]         = co[nt][0];
        pa[(d + 1) * NPOS + r0]     = co[nt][1];
        pa[(d) * NPOS + r0 + 8]     = co[nt][2];
        pa[(d + 1) * NPOS + r0 + 8] = co[nt][3];
    }
    if (tig == 0) {
        // col 24 of the l-MMA = row sum of p over this split's keys
        pl[sb * NPOS + r0]     = co[3][0];
        pl[sb * NPOS + r0 + 8] = co[3][2];
    }
}

// ---------------------------------------------------------------------------
extern "C" void kernel_launch(void* const* d_in, const int* in_sizes, int n_in,
                              void* d_out, int out_size)
{
    const float* x      = (const float*)d_in[0];
    const float* w_qkv  = (const float*)d_in[1];
    const float* w_dw   = (const float*)d_in[2];
    const float* w_proj = (const float*)d_in[3];
    float* out = (float*)d_out;

    float *pa, *plv;
    __half *qkv16, *q16, *k16, *v16;
    cudaGetSymbolAddress((void**)&pa, g_pacc);
    cudaGetSymbolAddress((void**)&plv, g_pl);
    cudaGetSymbolAddress((void**)&qkv16, g_qkv16);
    cudaGetSymbolAddress((void**)&q16, g_q16);
    cudaGetSymbolAddress((void**)&k16, g_k16);
    cudaGetSymbolAddress((void**)&v16, g_v16);

    pw1_mma_kernel<<<dim3(NPOS / 64, 576 / 64), 128>>>(qkv16, x, w_qkv);
    dwnorm_kernel<<<384, 256>>>(qkv16, w_dw, q16, k16, v16);
    attn_kernel<<<dim3(NPOS / 64, 8, KSPLIT), 128>>>(pa, plv, q16, k16, v16);
    pw2_mma_kernel<<<dim3(NPOS / 64, 192 / 64), 128>>>(out, pa, plv, w_proj);
}